// round 12
// baseline (speedup 1.0000x reference)
#include <cuda_runtime.h>
#include <cstdint>

#define NTOT 131072

__device__ __align__(16) float g_t[9170944];
__constant__ int c_OFF[12] = {0,4096,12288,28672,61440,126976,258048,520192,
                              1044480,2093056,3928064,6025216};
__constant__ int c_R[12] = {64,64,64,64,64,64,64,64,64,52,32,20};
__constant__ unsigned c_MUL[12] = {65536,65536,65536,65536,65536,65536,65536,65536,
                                   65536,80660,131072,209716};   // ceil(2^20/Rq)
#define ZERON 1044480   // levels 0-7 atomic region only

struct P { const float* u[12]; };

// ---------- helpers ----------
__device__ __forceinline__ uint32_t cvtf32(float f) {
    uint32_t r; asm("cvt.rna.tf32.f32 %0, %1;" : "=r"(r) : "f"(f)); return r;
}
__device__ __forceinline__ uint4 cvt4(float4 v) {
    uint4 o; o.x = cvtf32(v.x); o.y = cvtf32(v.y); o.z = cvtf32(v.z); o.w = cvtf32(v.w);
    return o;
}
__device__ __forceinline__ uint4 cvt4s(float4 v, float s2) {
    uint4 o; o.x = cvtf32(v.x * s2); o.y = cvtf32(v.y * s2);
    o.z = cvtf32(v.z * s2); o.w = cvtf32(v.w * s2);
    return o;
}
__device__ __forceinline__ void mma8(float* c, const uint32_t* a, uint32_t b0, uint32_t b1) {
    asm volatile("mma.sync.aligned.m16n8k8.row.col.f32.tf32.tf32.f32 "
        "{%0,%1,%2,%3}, {%4,%5,%6,%7}, {%8,%9}, {%0,%1,%2,%3};"
        : "+f"(c[0]), "+f"(c[1]), "+f"(c[2]), "+f"(c[3])
        : "r"(a[0]), "r"(a[1]), "r"(a[2]), "r"(a[3]), "r"(b0), "r"(b1));
}
__device__ __forceinline__ void red2(float* p, float a, float b) {
    asm volatile("red.global.add.v2.f32 [%0], {%1, %2};" :: "l"(p), "f"(a), "f"(b) : "memory");
}

__global__ void k_zero_t() {
    int i = blockIdx.x * blockDim.x + threadIdx.x;
    if (i < ZERON / 4) ((float4*)g_t)[i] = make_float4(0.f, 0.f, 0.f, 0.f);
}

// ================= phase 1: 256 s per CTA (2 chunks), K merged in registers =================
// smem: xs[2][32][132] (A row-major per chunk), us [128][68] (B, block-diag cols mod 2)
#define P1_SM ((8448 + 8704) * 4)
__global__ void __launch_bounds__(256, 2) k_p1(P p, const float* __restrict__ x) {
    extern __shared__ __align__(16) float sm[];
    float* xs = sm;               // 2 x 4224
    float* us = sm + 8448;
    const uint32_t* usu = (const uint32_t*)us;
    int tid = threadIdx.x, w = tid >> 5, lane = tid & 31;
    int g = lane >> 2, t4 = lane & 3;
    int wm = w >> 2, wg = w & 3;
    int slice2 = blockIdx.x;                       // 256-s super-slice

    for (int i = tid; i < 2048; i += 256) {        // stage both x chunks
        int c = i >> 10, j = i & 1023;
        int n = j >> 5, s4 = j & 31;
        float4 v = *(const float4*)(x + (size_t)n * NTOT + slice2 * 256 + c * 128 + 4 * s4);
        *(uint4*)(xs + c * 4224 + n * 132 + 4 * s4) = cvt4(v);
    }

    float4 pf[8];
    {   // prefetch U[0] chunk 0
        const float4* U0 = (const float4*)p.u[0] + (size_t)(slice2 * 2) * 2048;
        #pragma unroll
        for (int it = 0; it < 8; it++) pf[it] = U0[tid + 256 * it];
    }

    float acc[3][4];

    #pragma unroll 1
    for (int u = 0; u < 24; u++) {
        int L = u >> 1, c = u & 1;
        int sl = slice2 * 2 + c;
        int Rq = c_R[L] >> 2, tot = 128 * Rq;
        unsigned MUL = c_MUL[L];
        __syncthreads();                           // us free
        uint4 z = {0, 0, 0, 0};
        if (L == 9 && tid < 128) *(uint4*)(us + tid * 68 + 52) = z;
        if (L == 11 && tid < 128) {
            *(uint4*)(us + tid * 68 + 20) = z;
            *(uint4*)(us + tid * 68 + 44) = z;
        }
        #pragma unroll
        for (int it = 0; it < 8; it++) {           // STS U(u)
            int i = tid + 256 * it;
            if (i < tot) {
                int s = (int)(((unsigned)i * MUL) >> 20);
                int r4 = i - s * Rq;
                int col = (L <= 9) ? 4 * r4
                        : (L == 10 ? ((s >> 6) & 1) * 32 + 4 * r4
                                   : ((s >> 5) & 1) * 24 + 4 * r4);
                *(uint4*)(us + s * 68 + col) = cvt4(pf[it]);
            }
        }
        __syncthreads();
        if (u < 23) {                              // prefetch U(u+1)
            int L2 = (u + 1) >> 1, c2 = (u + 1) & 1;
            int tot2 = 128 * (c_R[L2] >> 2);
            const float4* U2 = (const float4*)p.u[L2]
                             + (size_t)(slice2 * 2 + c2) * (size_t)(32 * c_R[L2]);
            #pragma unroll
            for (int it = 0; it < 8; it++) {
                int i = tid + 256 * it;
                if (i < tot2) pf[it] = U2[i];
            }
        }

        int ntile = (L == 11) ? 3 : 2;
        int nb = (L == 11) ? 24 * (wg & 1) : 16 * wg;
        int kc0 = 0, kc1 = 16;
        if (L == 10) { kc0 = 8 * (wg >> 1); kc1 = kc0 + 8; }
        if (L == 11) { kc0 = 4 * wg;        kc1 = kc0 + 4; }

        if (c == 0 || L >= 9) {
            #pragma unroll
            for (int j = 0; j < 3; j++) { acc[j][0] = acc[j][1] = acc[j][2] = acc[j][3] = 0.f; }
        }

        const uint32_t* X = (const uint32_t*)(xs + c * 4224) + 16 * wm * 132;
        for (int kc = kc0; kc < kc1; kc++) {
            uint32_t a[4];
            int ko = 8 * kc + t4;
            a[0] = X[g * 132 + ko];       a[1] = X[(g + 8) * 132 + ko];
            a[2] = X[g * 132 + ko + 4];   a[3] = X[(g + 8) * 132 + ko + 4];
            const uint32_t* B0 = usu + (8 * kc + t4) * 68;
            const uint32_t* B1 = usu + (8 * kc + t4 + 4) * 68;
            #pragma unroll
            for (int j = 0; j < 3; j++)
                if (j < ntile) {
                    int np = nb + 8 * j + g;
                    mma8(acc[j], a, B0[np], B1[np]);
                }
        }

        if (L >= 9 || c == 1) {                    // flush
            int n1 = 16 * wm + g;
            #pragma unroll
            for (int j = 0; j < 3; j++) {
                if (j < ntile) {
                    int np = nb + 8 * j + 2 * t4;
                    if (L <= 7) {
                        int blk = slice2 >> (8 - L);
                        float* d0 = g_t + c_OFF[L] + (size_t)blk * 2048;
                        red2(d0 + n1 * 64 + np,       acc[j][0], acc[j][1]);
                        red2(d0 + (n1 + 8) * 64 + np, acc[j][2], acc[j][3]);
                    } else if (L == 8) {
                        float* d0 = g_t + c_OFF[8] + (size_t)slice2 * 2048;
                        *(float2*)(d0 + n1 * 64 + np)       = make_float2(acc[j][0], acc[j][1]);
                        *(float2*)(d0 + (n1 + 8) * 64 + np) = make_float2(acc[j][2], acc[j][3]);
                    } else if (L == 9) {
                        if (np < 56) {
                            float* d0 = g_t + c_OFF[9] + (size_t)sl * 1792;
                            *(float2*)(d0 + n1 * 56 + np)       = make_float2(acc[j][0], acc[j][1]);
                            *(float2*)(d0 + (n1 + 8) * 56 + np) = make_float2(acc[j][2], acc[j][3]);
                        }
                    } else if (L == 10) {
                        int blk = sl * 2 + (np >> 5), r = np & 31;
                        float* d0 = g_t + c_OFF[10] + (size_t)blk * 1024;
                        *(float2*)(d0 + n1 * 32 + r)       = make_float2(acc[j][0], acc[j][1]);
                        *(float2*)(d0 + (n1 + 8) * 32 + r) = make_float2(acc[j][2], acc[j][3]);
                    } else {
                        int blk = sl * 4 + wg, r = 8 * j + 2 * t4;
                        float* d0 = g_t + c_OFF[11] + (size_t)blk * 768;
                        *(float2*)(d0 + n1 * 24 + r)       = make_float2(acc[j][0], acc[j][1]);
                        *(float2*)(d0 + (n1 + 8) * 24 + r) = make_float2(acc[j][2], acc[j][3]);
                    }
                }
            }
        }
    }
}

// ---------- epilogue t-load helpers ----------
__device__ __forceinline__ int t_count(int L) {
    return (L <= 8 || L == 10) ? 512 : (L == 9 ? 448 : 768);
}
__device__ __forceinline__ float4 t_load(int L, int i, int slice) {
    const float4* b;
    if (L <= 8)      b = (const float4*)(g_t + c_OFF[L]) + (size_t)((slice >> (9 - L)) ^ 1) * 512 + i;
    else if (L == 9) b = (const float4*)(g_t + c_OFF[9]) + (size_t)(slice ^ 1) * 448 + i;
    else if (L == 10) {
        int j = i >> 8;
        b = (const float4*)(g_t + c_OFF[10]) + (size_t)(slice * 2 + (j ^ 1)) * 256 + (i & 255);
    } else {
        int j = i / 192;
        b = (const float4*)(g_t + c_OFF[11]) + (size_t)(slice * 4 + (j ^ 1)) * 192 + (i - 192 * j);
    }
    return *b;
}
__device__ __forceinline__ void t_store(float* r2, int L, int i, float4 v, float s2) {
    int off;
    if (L <= 8)      { int n = i >> 4, r4 = i & 15;            off = n * 68 + 4 * r4; }
    else if (L == 9) { int n = (int)(((unsigned)i * 74899u) >> 20); int r4 = i - 14 * n;
                       off = n * 68 + 4 * r4; }
    else if (L == 10){ int j = i >> 8, n = (i >> 3) & 31, r4 = i & 7;
                       off = j * 1152 + n * 36 + 4 * r4; }
    else             { int j = i / 192, rem = i - 192 * j;
                       int n = (int)(((unsigned)rem * 174763u) >> 20); int r4 = rem - 6 * n;
                       off = j * 1152 + n * 36 + 4 * r4; }
    *(uint4*)(r2 + off) = cvt4s(v, s2);
}

// ================= epilogue: out[n][s] = leaf + sum_L t_sib[n][r] * U[s][r] =================
#define E_SM ((8704 + 4608) * 4)
__global__ void __launch_bounds__(256, 2) k_epi(P p, const float* __restrict__ lb,
                                                const float* __restrict__ x,
                                                const float* __restrict__ sc,
                                                float* __restrict__ out) {
    extern __shared__ __align__(16) float sm[];
    float* r1 = sm;
    float* r2 = sm + 8704;
    const uint32_t* r1u = (const uint32_t*)r1;
    const uint32_t* r2u = (const uint32_t*)r2;
    int tid = threadIdx.x, w = tid >> 5, lane = tid & 31;
    int g = lane >> 2, t4 = lane & 3;
    int wm = w >> 2, wg = w & 3;
    int slice = blockIdx.x, s0 = slice * 128;
    float scv = __ldg(sc), s2 = scv * scv;

    for (int i = tid; i < 1024; i += 256) {               // xs[n][132]
        int n = i >> 5, s4 = i & 31;
        float4 v = *(const float4*)(x + (size_t)n * NTOT + s0 + 4 * s4);
        *(uint4*)(r1 + n * 132 + 4 * s4) = cvt4(v);
    }
    for (int i = tid; i < 1024; i += 256) {               // lbs[q][t][36]
        int q = i >> 8, t = (i >> 3) & 31, s4 = i & 7;
        float4 v = *(const float4*)(lb + (size_t)(slice * 4 + q) * 1024 + t * 32 + 4 * s4);
        *(uint4*)(r2 + q * 1152 + t * 36 + 4 * s4) = cvt4(v);
    }

    float4 pf[8];
    float4 pt[3];
    {   // prefetch U[0], t[0]
        const float4* U0 = (const float4*)p.u[0] + (size_t)slice * 2048;
        #pragma unroll
        for (int it = 0; it < 8; it++) pf[it] = U0[tid + 256 * it];
        #pragma unroll
        for (int it = 0; it < 3; it++) {
            int i = tid + 256 * it;
            if (i < 512) pt[it] = t_load(0, i, slice);
        }
    }
    __syncthreads();

    float acc[4][4];
    #pragma unroll
    for (int j = 0; j < 4; j++) { acc[j][0] = acc[j][1] = acc[j][2] = acc[j][3] = 0.f; }

    {   // leaf: warp n'-group wg == leaf block q
        const uint32_t* X = r1u + 16 * wm * 132 + 32 * wg;
        const uint32_t* Bq = r2u + wg * 1152;
        for (int kc = 0; kc < 4; kc++) {
            uint32_t a[4];
            int ko = 8 * kc + t4;
            a[0] = X[g * 132 + ko];     a[1] = X[(g + 8) * 132 + ko];
            a[2] = X[g * 132 + ko + 4]; a[3] = X[(g + 8) * 132 + ko + 4];
            #pragma unroll
            for (int j = 0; j < 4; j++) {
                int tl = 8 * j + g;
                mma8(acc[j], a, Bq[tl * 36 + ko], Bq[tl * 36 + ko + 4]);
            }
        }
    }

    #pragma unroll 1
    for (int L = 0; L < 12; L++) {
        int Rq = c_R[L] >> 2;
        int tot = 128 * Rq;
        unsigned MUL = c_MUL[L];
        __syncthreads();                                   // buffers free
        uint4 z = {0, 0, 0, 0};
        if (L == 9 && tid < 128)  *(uint4*)(r1 + tid * 68 + 52) = z;
        if (L == 11 && tid < 128) *(uint4*)(r1 + tid * 68 + 20) = z;
        #pragma unroll
        for (int it = 0; it < 8; it++) {                   // STS U[L]
            int i = tid + 256 * it;
            if (i < tot) {
                int s = (int)(((unsigned)i * MUL) >> 20);
                int r4 = i - s * Rq;
                *(uint4*)(r1 + s * 68 + 4 * r4) = cvt4(pf[it]);
            }
        }
        int tcnt = t_count(L);
        #pragma unroll
        for (int it = 0; it < 3; it++) {                   // STS t[L] (scaled)
            int i = tid + 256 * it;
            if (i < tcnt) t_store(r2, L, i, pt[it], s2);
        }
        __syncthreads();
        if (L < 11) {                                      // prefetch next
            int tot2 = 128 * (c_R[L + 1] >> 2);
            const float4* U2 = (const float4*)p.u[L + 1] + (size_t)slice * tot2;
            #pragma unroll
            for (int it = 0; it < 8; it++) {
                int i = tid + 256 * it;
                if (i < tot2) pf[it] = U2[i];
            }
            int tc2 = t_count(L + 1);
            #pragma unroll
            for (int it = 0; it < 3; it++) {
                int i = tid + 256 * it;
                if (i < tc2) pt[it] = t_load(L + 1, i, slice);
            }
        }

        int astride = (L <= 9) ? 68 : 36;
        int nch = (L <= 8) ? 8 : (L == 9 ? 7 : (L == 10 ? 4 : 3));
        const uint32_t* A = r2u;
        if (L == 10) A = r2u + (wg >> 1) * 1152;
        else if (L == 11) A = r2u + wg * 1152;
        const uint32_t* Arow = A + 16 * wm * astride;
        const uint32_t* Bs = r1u + 32 * wg * 68;
        for (int kc = 0; kc < nch; kc++) {
            uint32_t a[4];
            int ko = 8 * kc + t4;
            a[0] = Arow[g * astride + ko];     a[1] = Arow[(g + 8) * astride + ko];
            a[2] = Arow[g * astride + ko + 4]; a[3] = Arow[(g + 8) * astride + ko + 4];
            #pragma unroll
            for (int j = 0; j < 4; j++) {
                int sl = 8 * j + g;
                mma8(acc[j], a, Bs[sl * 68 + ko], Bs[sl * 68 + ko + 4]);
            }
        }
    }

    int n1 = 16 * wm + g;
    #pragma unroll
    for (int j = 0; j < 4; j++) {
        int sl = s0 + 32 * wg + 8 * j + 2 * t4;
        *(float2*)(out + (size_t)n1 * NTOT + sl)       = make_float2(acc[j][0], acc[j][1]);
        *(float2*)(out + (size_t)(n1 + 8) * NTOT + sl) = make_float2(acc[j][2], acc[j][3]);
    }
}

// ---------- driver ----------
extern "C" void kernel_launch(void* const* d_in, const int* in_sizes, int n_in,
                              void* d_out, int out_size) {
    (void)in_sizes; (void)n_in; (void)out_size;
    const float* x  = (const float*)d_in[0];
    const float* lb = (const float*)d_in[1];
    const float* sc = (const float*)d_in[2];
    P p;
    for (int l = 0; l < 12; l++) p.u[l] = (const float*)d_in[3 + l];
    float* out = (float*)d_out;

    cudaFuncSetAttribute(k_p1,  cudaFuncAttributeMaxDynamicSharedMemorySize, P1_SM);
    cudaFuncSetAttribute(k_epi, cudaFuncAttributeMaxDynamicSharedMemorySize, E_SM);

    k_zero_t<<<(ZERON / 4 + 255) / 256, 256>>>();
    k_p1<<<512, 256, P1_SM>>>(p, x);
    k_epi<<<1024, 256, E_SM>>>(p, lb, x, sc, out);
}

// round 13
// speedup vs baseline: 1.2742x; 1.2742x over previous
#include <cuda_runtime.h>
#include <cstdint>

#define NTOT 131072

__device__ __align__(16) float g_t[9170944];
__constant__ int c_OFF[12] = {0,4096,12288,28672,61440,126976,258048,520192,
                              1044480,2093056,3928064,6025216};
__constant__ int c_R[12] = {64,64,64,64,64,64,64,64,64,52,32,20};
__constant__ unsigned c_MUL[12] = {65536,65536,65536,65536,65536,65536,65536,65536,
                                   65536,80660,131072,209716};   // ceil(2^20/Rq)
#define ZERON 2093056   // levels 0-8 atomic region

struct P { const float* u[12]; };

// ---------- helpers ----------
__device__ __forceinline__ uint32_t cvtf32(float f) {
    uint32_t r; asm("cvt.rna.tf32.f32 %0, %1;" : "=r"(r) : "f"(f)); return r;
}
__device__ __forceinline__ uint4 cvt4(float4 v) {
    uint4 o; o.x = cvtf32(v.x); o.y = cvtf32(v.y); o.z = cvtf32(v.z); o.w = cvtf32(v.w);
    return o;
}
__device__ __forceinline__ uint4 cvt4s(float4 v, float s2) {
    uint4 o; o.x = cvtf32(v.x * s2); o.y = cvtf32(v.y * s2);
    o.z = cvtf32(v.z * s2); o.w = cvtf32(v.w * s2);
    return o;
}
__device__ __forceinline__ void mma8(float* c, const uint32_t* a, uint32_t b0, uint32_t b1) {
    asm volatile("mma.sync.aligned.m16n8k8.row.col.f32.tf32.tf32.f32 "
        "{%0,%1,%2,%3}, {%4,%5,%6,%7}, {%8,%9}, {%0,%1,%2,%3};"
        : "+f"(c[0]), "+f"(c[1]), "+f"(c[2]), "+f"(c[3])
        : "r"(a[0]), "r"(a[1]), "r"(a[2]), "r"(a[3]), "r"(b0), "r"(b1));
}
__device__ __forceinline__ void red2(float* p, float a, float b) {
    asm volatile("red.global.add.v2.f32 [%0], {%1, %2};" :: "l"(p), "f"(a), "f"(b) : "memory");
}
__device__ __forceinline__ uint32_t smem_u32(const void* p) {
    uint32_t a; asm("{ .reg .u64 t; cvta.to.shared.u64 t, %1; cvt.u32.u64 %0, t; }" : "=r"(a) : "l"(p));
    return a;
}
__device__ __forceinline__ void cpa16(uint32_t dst, const void* src) {
    asm volatile("cp.async.cg.shared.global [%0], [%1], 16;" :: "r"(dst), "l"(src) : "memory");
}
__device__ __forceinline__ void cpa_commit() { asm volatile("cp.async.commit_group;" ::: "memory"); }
__device__ __forceinline__ void cpa_wait0()  { asm volatile("cp.async.wait_group 0;" ::: "memory"); }

__global__ void k_zero_t() {
    int i = blockIdx.x * blockDim.x + threadIdx.x;
    if (i < ZERON / 4) ((float4*)g_t)[i] = make_float4(0.f, 0.f, 0.f, 0.f);
}

// stage U[L] for given slice into smem buffer (word base dstw), p1 layout (block-diag cols)
__device__ __forceinline__ void p1_issueU(uint32_t smb, uint32_t dstw, const float* U,
                                          int L, int slice, int tid) {
    int Rq = c_R[L] >> 2, tot = 128 * Rq;
    unsigned MUL = c_MUL[L];
    const float4* U4 = (const float4*)U + (size_t)slice * (size_t)(32 * c_R[L]);
    #pragma unroll
    for (int it = 0; it < 8; it++) {
        int i = tid + 256 * it;
        if (i < tot) {
            int s = (int)(((unsigned)i * MUL) >> 20);
            int r4 = i - s * Rq;
            int col = (L <= 9) ? 4 * r4
                    : (L == 10 ? ((s >> 6) & 1) * 32 + 4 * r4
                               : ((s >> 5) & 1) * 24 + 4 * r4);
            cpa16(smb + (dstw + s * 68 + col) * 4, U4 + i);
        }
    }
}
// epi layout: straight cols
__device__ __forceinline__ void epi_issueU(uint32_t smb, uint32_t dstw, const float* U,
                                           int L, int slice, int tid) {
    int Rq = c_R[L] >> 2, tot = 128 * Rq;
    unsigned MUL = c_MUL[L];
    const float4* U4 = (const float4*)U + (size_t)slice * (size_t)(32 * c_R[L]);
    #pragma unroll
    for (int it = 0; it < 8; it++) {
        int i = tid + 256 * it;
        if (i < tot) {
            int s = (int)(((unsigned)i * MUL) >> 20);
            int r4 = i - s * Rq;
            cpa16(smb + (dstw + s * 68 + 4 * r4) * 4, U4 + i);
        }
    }
}

// ================= phase 1: t'[n][r] = x[n][s] * U[s][r], per 128-s slice =================
// smem words: xs[4224] | usA[8704] | usB[8704]
#define P1_SM (21632 * 4)
__global__ void __launch_bounds__(256, 2) k_p1(P p, const float* __restrict__ x) {
    extern __shared__ __align__(16) float sm[];
    float* xs = sm;
    uint32_t smb = smem_u32(sm);
    int tid = threadIdx.x, w = tid >> 5, lane = tid & 31;
    int g = lane >> 2, t4 = lane & 3;
    int wm = w >> 2, wg = w & 3;
    int slice = blockIdx.x, s0 = slice * 128;

    // G0: xs + U0 -> bufA
    #pragma unroll
    for (int it = 0; it < 4; it++) {
        int i = tid + 256 * it;
        int n = i >> 5, s4 = i & 31;
        cpa16(smb + (n * 132 + 4 * s4) * 4, x + (size_t)n * NTOT + s0 + 4 * s4);
    }
    p1_issueU(smb, 4224, p.u[0], 0, slice, tid);
    cpa_commit();
    cpa_wait0();
    __syncthreads();
    #pragma unroll
    for (int it = 0; it < 4; it++) {               // cvt xs in place (once)
        int i = tid + 256 * it;
        int off = (i >> 5) * 132 + 4 * (i & 31);
        float4 v = *(float4*)(xs + off);
        *(uint4*)(xs + off) = cvt4(v);
    }
    __syncthreads();

    #pragma unroll 1
    for (int L = 0; L < 12; L++) {
        int cur = L & 1;
        uint32_t curw = 4224 + cur * 8704;
        if (L < 11) {                              // stage next level into other buffer
            uint32_t nxtw = 4224 + (cur ^ 1) * 8704;
            float* nx = sm + nxtw;
            uint4 z = {0, 0, 0, 0};
            int L2 = L + 1;
            if (L2 == 9 && tid < 128) *(uint4*)(nx + tid * 68 + 52) = z;
            if (L2 == 11 && tid < 128) {
                *(uint4*)(nx + tid * 68 + 20) = z;
                *(uint4*)(nx + tid * 68 + 44) = z;
            }
            p1_issueU(smb, nxtw, p.u[L2], L2, slice, tid);
            cpa_commit();
        }

        int ntile = (L == 11) ? 3 : 2;
        int nb = (L == 11) ? 24 * (wg & 1) : 16 * wg;
        int kc0 = 0, kc1 = 16;
        if (L == 10) { kc0 = 8 * (wg >> 1); kc1 = kc0 + 8; }
        if (L == 11) { kc0 = 4 * wg;        kc1 = kc0 + 4; }

        float acc[3][4];
        #pragma unroll
        for (int j = 0; j < 3; j++) { acc[j][0] = acc[j][1] = acc[j][2] = acc[j][3] = 0.f; }

        const uint32_t* X = (const uint32_t*)xs + 16 * wm * 132;
        const float* Bf = sm + curw;
        for (int kc = kc0; kc < kc1; kc++) {
            uint32_t a[4];
            int ko = 8 * kc + t4;
            a[0] = X[g * 132 + ko];       a[1] = X[(g + 8) * 132 + ko];
            a[2] = X[g * 132 + ko + 4];   a[3] = X[(g + 8) * 132 + ko + 4];
            const float* B0 = Bf + ko * 68;
            const float* B1 = Bf + (ko + 4) * 68;
            #pragma unroll
            for (int j = 0; j < 3; j++)
                if (j < ntile) {
                    int np = nb + 8 * j + g;
                    mma8(acc[j], a, cvtf32(B0[np]), cvtf32(B1[np]));
                }
        }

        int n1 = 16 * wm + g;
        #pragma unroll
        for (int j = 0; j < 3; j++) {
            if (j < ntile) {
                int np = nb + 8 * j + 2 * t4;
                if (L <= 8) {
                    int blk = slice >> (9 - L);
                    float* d0 = g_t + c_OFF[L] + (size_t)blk * 2048;
                    red2(d0 + n1 * 64 + np,       acc[j][0], acc[j][1]);
                    red2(d0 + (n1 + 8) * 64 + np, acc[j][2], acc[j][3]);
                } else if (L == 9) {
                    if (np < 56) {
                        float* d0 = g_t + c_OFF[9] + (size_t)slice * 1792;
                        *(float2*)(d0 + n1 * 56 + np)       = make_float2(acc[j][0], acc[j][1]);
                        *(float2*)(d0 + (n1 + 8) * 56 + np) = make_float2(acc[j][2], acc[j][3]);
                    }
                } else if (L == 10) {
                    int blk = slice * 2 + (np >> 5), r = np & 31;
                    float* d0 = g_t + c_OFF[10] + (size_t)blk * 1024;
                    *(float2*)(d0 + n1 * 32 + r)       = make_float2(acc[j][0], acc[j][1]);
                    *(float2*)(d0 + (n1 + 8) * 32 + r) = make_float2(acc[j][2], acc[j][3]);
                } else {
                    int blk = slice * 4 + wg, r = 8 * j + 2 * t4;
                    float* d0 = g_t + c_OFF[11] + (size_t)blk * 768;
                    *(float2*)(d0 + n1 * 24 + r)       = make_float2(acc[j][0], acc[j][1]);
                    *(float2*)(d0 + (n1 + 8) * 24 + r) = make_float2(acc[j][2], acc[j][3]);
                }
            }
        }
        if (L < 11) { cpa_wait0(); __syncthreads(); }
    }
}

// ---------- epilogue t helpers ----------
__device__ __forceinline__ int t_count(int L) {
    return (L <= 8 || L == 10) ? 512 : (L == 9 ? 448 : 768);
}
__device__ __forceinline__ float4 t_load(int L, int i, int slice) {
    const float4* b;
    if (L <= 8)      b = (const float4*)(g_t + c_OFF[L]) + (size_t)((slice >> (9 - L)) ^ 1) * 512 + i;
    else if (L == 9) b = (const float4*)(g_t + c_OFF[9]) + (size_t)(slice ^ 1) * 448 + i;
    else if (L == 10) {
        int j = i >> 8;
        b = (const float4*)(g_t + c_OFF[10]) + (size_t)(slice * 2 + (j ^ 1)) * 256 + (i & 255);
    } else {
        int j = i / 192;
        b = (const float4*)(g_t + c_OFF[11]) + (size_t)(slice * 4 + (j ^ 1)) * 192 + (i - 192 * j);
    }
    return *b;
}
__device__ __forceinline__ void t_store(float* r2, int L, int i, float4 v, float s2) {
    int off;
    if (L <= 8)      { int n = i >> 4, r4 = i & 15;            off = n * 68 + 4 * r4; }
    else if (L == 9) { int n = (int)(((unsigned)i * 74899u) >> 20); int r4 = i - 14 * n;
                       off = n * 68 + 4 * r4; }
    else if (L == 10){ int j = i >> 8, n = (i >> 3) & 31, r4 = i & 7;
                       off = j * 1152 + n * 36 + 4 * r4; }
    else             { int j = i / 192, rem = i - 192 * j;
                       int n = (int)(((unsigned)rem * 174763u) >> 20); int r4 = rem - 6 * n;
                       off = j * 1152 + n * 36 + 4 * r4; }
    *(uint4*)(r2 + off) = cvt4s(v, s2);
}

// ================= epilogue: out[n][s] = leaf + sum_L t_sib[n][r] * U[s][r] =================
// smem words: xs[4224] | usA[8704] | usB[8704] | r2[4608]
#define E_SM (26240 * 4)
__global__ void __launch_bounds__(256, 2) k_epi(P p, const float* __restrict__ lb,
                                                const float* __restrict__ x,
                                                const float* __restrict__ sc,
                                                float* __restrict__ out) {
    extern __shared__ __align__(16) float sm[];
    float* xs = sm;
    float* r2 = sm + 21632;
    uint32_t smb = smem_u32(sm);
    int tid = threadIdx.x, w = tid >> 5, lane = tid & 31;
    int g = lane >> 2, t4 = lane & 3;
    int wm = w >> 2, wg = w & 3;
    int slice = blockIdx.x, s0 = slice * 128;
    float scv = __ldg(sc), s2 = scv * scv;

    // G0: xs + lbs + U0->bufA
    #pragma unroll
    for (int it = 0; it < 4; it++) {
        int i = tid + 256 * it;
        int n = i >> 5, s4 = i & 31;
        cpa16(smb + (n * 132 + 4 * s4) * 4, x + (size_t)n * NTOT + s0 + 4 * s4);
    }
    #pragma unroll
    for (int it = 0; it < 4; it++) {
        int i = tid + 256 * it;
        int q = i >> 8, t = (i >> 3) & 31, s4 = i & 7;
        cpa16(smb + (21632 + q * 1152 + t * 36 + 4 * s4) * 4,
              lb + (size_t)(slice * 4 + q) * 1024 + t * 32 + 4 * s4);
    }
    epi_issueU(smb, 4224, p.u[0], 0, slice, tid);
    cpa_commit();

    float4 pt[3];
    #pragma unroll
    for (int it = 0; it < 3; it++) {
        int i = tid + 256 * it;
        if (i < 512) pt[it] = t_load(0, i, slice);
    }
    cpa_wait0();
    __syncthreads();

    float acc[4][4];
    #pragma unroll
    for (int j = 0; j < 4; j++) { acc[j][0] = acc[j][1] = acc[j][2] = acc[j][3] = 0.f; }

    {   // leaf: A = xs (cvt at load), B = lbs in r2 (cvt at load)
        const uint32_t* X = (const uint32_t*)xs + 16 * wm * 132 + 32 * wg;
        const float* Bq = r2 + wg * 1152;
        for (int kc = 0; kc < 4; kc++) {
            uint32_t a[4];
            int ko = 8 * kc + t4;
            a[0] = cvtf32(((const float*)X)[g * 132 + ko]);
            a[1] = cvtf32(((const float*)X)[(g + 8) * 132 + ko]);
            a[2] = cvtf32(((const float*)X)[g * 132 + ko + 4]);
            a[3] = cvtf32(((const float*)X)[(g + 8) * 132 + ko + 4]);
            #pragma unroll
            for (int j = 0; j < 4; j++) {
                int tl = 8 * j + g;
                mma8(acc[j], a, cvtf32(Bq[tl * 36 + ko]), cvtf32(Bq[tl * 36 + ko + 4]));
            }
        }
    }
    __syncthreads();
    #pragma unroll
    for (int it = 0; it < 3; it++) {               // t_store(0)
        int i = tid + 256 * it;
        if (i < 512) t_store(r2, 0, i, pt[it], s2);
    }
    __syncthreads();

    #pragma unroll 1
    for (int L = 0; L < 12; L++) {
        int cur = L & 1;
        uint32_t curw = 4224 + cur * 8704;
        if (L < 11) {
            uint32_t nxtw = 4224 + (cur ^ 1) * 8704;
            float* nx = sm + nxtw;
            uint4 z = {0, 0, 0, 0};
            int L2 = L + 1;
            if (L2 == 9 && tid < 128)  *(uint4*)(nx + tid * 68 + 52) = z;
            if (L2 == 11 && tid < 128) *(uint4*)(nx + tid * 68 + 20) = z;
            epi_issueU(smb, nxtw, p.u[L2], L2, slice, tid);
            cpa_commit();
            int tc2 = t_count(L2);
            #pragma unroll
            for (int it = 0; it < 3; it++) {
                int i = tid + 256 * it;
                if (i < tc2) pt[it] = t_load(L2, i, slice);
            }
        }

        int astride = (L <= 9) ? 68 : 36;
        int nch = (L <= 8) ? 8 : (L == 9 ? 7 : (L == 10 ? 4 : 3));
        const float* A = r2;
        if (L == 10) A = r2 + (wg >> 1) * 1152;
        else if (L == 11) A = r2 + wg * 1152;
        const uint32_t* Arow = (const uint32_t*)A + 16 * wm * astride;
        const float* Bs = sm + curw + 32 * wg * 68;
        for (int kc = 0; kc < nch; kc++) {
            uint32_t a[4];
            int ko = 8 * kc + t4;
            a[0] = Arow[g * astride + ko];     a[1] = Arow[(g + 8) * astride + ko];
            a[2] = Arow[g * astride + ko + 4]; a[3] = Arow[(g + 8) * astride + ko + 4];
            #pragma unroll
            for (int j = 0; j < 4; j++) {
                int sl = 8 * j + g;
                mma8(acc[j], a, cvtf32(Bs[sl * 68 + ko]), cvtf32(Bs[sl * 68 + ko + 4]));
            }
        }

        if (L < 11) {
            cpa_wait0();
            __syncthreads();
            int tc2 = t_count(L + 1);
            #pragma unroll
            for (int it = 0; it < 3; it++) {
                int i = tid + 256 * it;
                if (i < tc2) t_store(r2, L + 1, i, pt[it], s2);
            }
            __syncthreads();
        }
    }

    int n1 = 16 * wm + g;
    #pragma unroll
    for (int j = 0; j < 4; j++) {
        int sl = s0 + 32 * wg + 8 * j + 2 * t4;
        *(float2*)(out + (size_t)n1 * NTOT + sl)       = make_float2(acc[j][0], acc[j][1]);
        *(float2*)(out + (size_t)(n1 + 8) * NTOT + sl) = make_float2(acc[j][2], acc[j][3]);
    }
}

// ---------- driver ----------
extern "C" void kernel_launch(void* const* d_in, const int* in_sizes, int n_in,
                              void* d_out, int out_size) {
    (void)in_sizes; (void)n_in; (void)out_size;
    const float* x  = (const float*)d_in[0];
    const float* lb = (const float*)d_in[1];
    const float* sc = (const float*)d_in[2];
    P p;
    for (int l = 0; l < 12; l++) p.u[l] = (const float*)d_in[3 + l];
    float* out = (float*)d_out;

    cudaFuncSetAttribute(k_p1,  cudaFuncAttributeMaxDynamicSharedMemorySize, P1_SM);
    cudaFuncSetAttribute(k_epi, cudaFuncAttributeMaxDynamicSharedMemorySize, E_SM);

    k_zero_t<<<(ZERON / 4 + 255) / 256, 256>>>();
    k_p1<<<1024, 256, P1_SM>>>(p, x);
    k_epi<<<1024, 256, E_SM>>>(p, lb, x, sc, out);
}

// round 14
// speedup vs baseline: 1.3857x; 1.0875x over previous
#include <cuda_runtime.h>
#include <cstdint>

#define NTOT 131072

__device__ __align__(16) float g_t[9170944];
__constant__ int c_OFF[12] = {0,4096,12288,28672,61440,126976,258048,520192,
                              1044480,2093056,3928064,6025216};
__constant__ int c_R[12] = {64,64,64,64,64,64,64,64,64,52,32,20};
__constant__ unsigned c_MUL[12] = {65536,65536,65536,65536,65536,65536,65536,65536,
                                   65536,80660,131072,209716};   // ceil(2^20/Rq)
#define ZERON 2093056   // levels 0-8 atomic region

struct P { const float* u[12]; };

// ---------- helpers ----------
__device__ __forceinline__ uint32_t pkh2(float lo, float hi) {   // half2 {lo, hi}
    uint32_t r; asm("cvt.rn.f16x2.f32 %0, %1, %2;" : "=r"(r) : "f"(hi), "f"(lo)); return r;
}
__device__ __forceinline__ uint2 pk4(float4 v) {
    uint2 o; o.x = pkh2(v.x, v.y); o.y = pkh2(v.z, v.w); return o;
}
__device__ __forceinline__ uint2 pk4s(float4 v, float s) {
    uint2 o; o.x = pkh2(v.x * s, v.y * s); o.y = pkh2(v.z * s, v.w * s); return o;
}
__device__ __forceinline__ void mma16(float* c, const uint32_t* a, uint32_t b0, uint32_t b1) {
    asm volatile("mma.sync.aligned.m16n8k16.row.col.f32.f16.f16.f32 "
        "{%0,%1,%2,%3}, {%4,%5,%6,%7}, {%8,%9}, {%0,%1,%2,%3};"
        : "+f"(c[0]), "+f"(c[1]), "+f"(c[2]), "+f"(c[3])
        : "r"(a[0]), "r"(a[1]), "r"(a[2]), "r"(a[3]), "r"(b0), "r"(b1));
}
__device__ __forceinline__ void red2(float* p, float a, float b) {
    asm volatile("red.global.add.v2.f32 [%0], {%1, %2};" :: "l"(p), "f"(a), "f"(b) : "memory");
}
__device__ __forceinline__ uint32_t smem_u32(const void* p) {
    uint32_t a; asm("{ .reg .u64 t; cvta.to.shared.u64 t, %1; cvt.u32.u64 %0, t; }" : "=r"(a) : "l"(p));
    return a;
}
__device__ __forceinline__ void cpa16(uint32_t dst, const void* src) {
    asm volatile("cp.async.cg.shared.global [%0], [%1], 16;" :: "r"(dst), "l"(src) : "memory");
}
__device__ __forceinline__ void cpa_commit() { asm volatile("cp.async.commit_group;" ::: "memory"); }
__device__ __forceinline__ void cpa_wait0()  { asm volatile("cp.async.wait_group 0;" ::: "memory"); }

__global__ void k_zero_t() {
    int i = blockIdx.x * blockDim.x + threadIdx.x;
    if (i < ZERON / 4) ((float4*)g_t)[i] = make_float4(0.f, 0.f, 0.f, 0.f);
}

// stage U[L] (fp32) via cp.async: p1 layout [s][68] with block-diag cols
__device__ __forceinline__ void p1_issueU(uint32_t smb, uint32_t dstw, const float* U,
                                          int L, int slice, int tid) {
    int Rq = c_R[L] >> 2, tot = 128 * Rq;
    unsigned MUL = c_MUL[L];
    const float4* U4 = (const float4*)U + (size_t)slice * (size_t)(32 * c_R[L]);
    #pragma unroll
    for (int it = 0; it < 8; it++) {
        int i = tid + 256 * it;
        if (i < tot) {
            int s = (int)(((unsigned)i * MUL) >> 20);
            int r4 = i - s * Rq;
            int col = (L <= 9) ? 4 * r4
                    : (L == 10 ? ((s >> 6) & 1) * 32 + 4 * r4
                               : ((s >> 5) & 1) * 24 + 4 * r4);
            cpa16(smb + (dstw + s * 68 + col) * 4, U4 + i);
        }
    }
}
// epi layout [s][72] straight cols
__device__ __forceinline__ void epi_issueU(uint32_t smb, uint32_t dstw, const float* U,
                                           int L, int slice, int tid) {
    int Rq = c_R[L] >> 2, tot = 128 * Rq;
    unsigned MUL = c_MUL[L];
    const float4* U4 = (const float4*)U + (size_t)slice * (size_t)(32 * c_R[L]);
    #pragma unroll
    for (int it = 0; it < 8; it++) {
        int i = tid + 256 * it;
        if (i < tot) {
            int s = (int)(((unsigned)i * MUL) >> 20);
            int r4 = i - s * Rq;
            cpa16(smb + (dstw + s * 72 + 4 * r4) * 4, U4 + i);
        }
    }
}

// ================= phase 1: t'[n][r] = x[n][s] U[s][r] =================
// words: X2[32][68] half2 | usA[8704] fp32 | usB[8704] fp32
#define P1_SM (19584 * 4)
__global__ void __launch_bounds__(256, 2) k_p1(P p, const float* __restrict__ x) {
    extern __shared__ __align__(16) uint32_t sm[];
    uint32_t* X2 = sm;
    uint32_t smb = smem_u32(sm);
    int tid = threadIdx.x, w = tid >> 5, lane = tid & 31;
    int g = lane >> 2, t4 = lane & 3;
    int wm = w >> 2, wg = w & 3;
    int slice = blockIdx.x, s0 = slice * 128;

    p1_issueU(smb, 2176, p.u[0], 0, slice, tid);
    cpa_commit();
    #pragma unroll
    for (int it = 0; it < 4; it++) {               // x -> packed half2 [n][68]
        int i = tid + 256 * it;
        int n = i >> 5, s4 = i & 31;
        float4 v = *(const float4*)(x + (size_t)n * NTOT + s0 + 4 * s4);
        *(uint2*)(X2 + n * 68 + 2 * s4) = pk4(v);
    }
    cpa_wait0();
    __syncthreads();

    #pragma unroll 1
    for (int L = 0; L < 12; L++) {
        int cur = L & 1;
        uint32_t curw = 2176 + cur * 8704;
        if (L < 11) {
            uint32_t nxtw = 2176 + (cur ^ 1) * 8704;
            float* nx = (float*)(sm + nxtw);
            uint4 z = {0, 0, 0, 0};
            int L2 = L + 1;
            if (L2 == 9 && tid < 128) *(uint4*)(nx + tid * 68 + 52) = z;
            if (L2 == 11 && tid < 128) {
                *(uint4*)(nx + tid * 68 + 20) = z;
                *(uint4*)(nx + tid * 68 + 44) = z;
            }
            p1_issueU(smb, nxtw, p.u[L2], L2, slice, tid);
            cpa_commit();
        }

        int ntile = (L == 11) ? 3 : 2;
        int nb = (L == 11) ? 24 * (wg & 1) : 16 * wg;
        int kc0 = 0, kc1 = 8;
        if (L == 10) { kc0 = 4 * (wg >> 1); kc1 = kc0 + 4; }
        if (L == 11) { kc0 = 2 * wg;        kc1 = kc0 + 2; }

        float acc[3][4];
        #pragma unroll
        for (int j = 0; j < 3; j++) { acc[j][0] = acc[j][1] = acc[j][2] = acc[j][3] = 0.f; }

        const uint32_t* X = X2 + 16 * wm * 68;
        const float* Bf = (const float*)(sm + curw);
        for (int kc = kc0; kc < kc1; kc++) {
            uint32_t a[4];
            int k2 = t4 + 8 * kc;
            a[0] = X[g * 68 + k2];       a[1] = X[(g + 8) * 68 + k2];
            a[2] = X[g * 68 + k2 + 4];   a[3] = X[(g + 8) * 68 + k2 + 4];
            const float* Br0 = Bf + (16 * kc + 2 * t4) * 68;
            #pragma unroll
            for (int j = 0; j < 3; j++)
                if (j < ntile) {
                    int np = nb + 8 * j + g;
                    uint32_t b0 = pkh2(Br0[np],           Br0[np + 68]);
                    uint32_t b1 = pkh2(Br0[np + 8 * 68],  Br0[np + 9 * 68]);
                    mma16(acc[j], a, b0, b1);
                }
        }

        int n1 = 16 * wm + g;
        #pragma unroll
        for (int j = 0; j < 3; j++) {
            if (j < ntile) {
                int np = nb + 8 * j + 2 * t4;
                if (L <= 8) {
                    int blk = slice >> (9 - L);
                    float* d0 = g_t + c_OFF[L] + (size_t)blk * 2048;
                    red2(d0 + n1 * 64 + np,       acc[j][0], acc[j][1]);
                    red2(d0 + (n1 + 8) * 64 + np, acc[j][2], acc[j][3]);
                } else if (L == 9) {
                    if (np < 56) {
                        float* d0 = g_t + c_OFF[9] + (size_t)slice * 1792;
                        *(float2*)(d0 + n1 * 56 + np)       = make_float2(acc[j][0], acc[j][1]);
                        *(float2*)(d0 + (n1 + 8) * 56 + np) = make_float2(acc[j][2], acc[j][3]);
                    }
                } else if (L == 10) {
                    int blk = slice * 2 + (np >> 5), r = np & 31;
                    float* d0 = g_t + c_OFF[10] + (size_t)blk * 1024;
                    *(float2*)(d0 + n1 * 32 + r)       = make_float2(acc[j][0], acc[j][1]);
                    *(float2*)(d0 + (n1 + 8) * 32 + r) = make_float2(acc[j][2], acc[j][3]);
                } else {
                    int blk = slice * 4 + wg, r = 8 * j + 2 * t4;
                    float* d0 = g_t + c_OFF[11] + (size_t)blk * 768;
                    *(float2*)(d0 + n1 * 24 + r)       = make_float2(acc[j][0], acc[j][1]);
                    *(float2*)(d0 + (n1 + 8) * 24 + r) = make_float2(acc[j][2], acc[j][3]);
                }
            }
        }
        if (L < 11) { cpa_wait0(); __syncthreads(); }
    }
}

// ---------- epilogue t helpers ----------
__device__ __forceinline__ int t_count(int L) {
    return (L <= 8 || L == 10) ? 512 : (L == 9 ? 448 : 768);
}
__device__ __forceinline__ float4 t_load(int L, int i, int slice) {
    const float4* b;
    if (L <= 8)      b = (const float4*)(g_t + c_OFF[L]) + (size_t)((slice >> (9 - L)) ^ 1) * 512 + i;
    else if (L == 9) b = (const float4*)(g_t + c_OFF[9]) + (size_t)(slice ^ 1) * 448 + i;
    else if (L == 10) {
        int j = i >> 8;
        b = (const float4*)(g_t + c_OFF[10]) + (size_t)(slice * 2 + (j ^ 1)) * 256 + (i & 255);
    } else {
        int j = i / 192;
        b = (const float4*)(g_t + c_OFF[11]) + (size_t)(slice * 4 + (j ^ 1)) * 192 + (i - 192 * j);
    }
    return *b;
}
// T2 half2 layouts: L<=9: [n][36]; L10: [2][32][20]; L11: [4][32][20]
__device__ __forceinline__ void t_store(uint32_t* T2, int L, int i, float4 v, float s2) {
    int off;
    if (L <= 8)      { int n = i >> 4, r4 = i & 15;                off = n * 36 + 2 * r4; }
    else if (L == 9) { int n = (int)(((unsigned)i * 74899u) >> 20); int r4 = i - 14 * n;
                       off = n * 36 + 2 * r4; }
    else if (L == 10){ int j = i >> 8, n = (i >> 3) & 31, r4 = i & 7;
                       off = j * 640 + n * 20 + 2 * r4; }
    else             { int j = i / 192, rem = i - 192 * j;
                       int n = (int)(((unsigned)rem * 174763u) >> 20); int r4 = rem - 6 * n;
                       off = j * 640 + n * 20 + 2 * r4; }
    *(uint2*)(T2 + off) = pk4s(v, s2);
}

// ================= epilogue: out[n][s] = leaf + sum_L t_sib[n][r] U[s][r] =================
// words: X2[2176] | usA[9216] | usB[9216] | T2[2560] | LB2[2560]  = 25728
#define E_SM (25728 * 4)
__global__ void __launch_bounds__(256, 2) k_epi(P p, const float* __restrict__ lb,
                                                const float* __restrict__ x,
                                                const float* __restrict__ sc,
                                                float* __restrict__ out) {
    extern __shared__ __align__(16) uint32_t sm[];
    uint32_t* X2 = sm;
    uint32_t* T2 = sm + 20608;
    uint32_t* LB2 = sm + 23168;
    uint32_t smb = smem_u32(sm);
    int tid = threadIdx.x, w = tid >> 5, lane = tid & 31;
    int g = lane >> 2, t4 = lane & 3;
    int wm = w >> 2, wg = w & 3;
    int slice = blockIdx.x, s0 = slice * 128;
    float scv = __ldg(sc), s2 = scv * scv;

    epi_issueU(smb, 2176, p.u[0], 0, slice, tid);
    cpa_commit();
    #pragma unroll
    for (int it = 0; it < 4; it++) {               // x -> half2 [n][68]
        int i = tid + 256 * it;
        int n = i >> 5, s4 = i & 31;
        float4 v = *(const float4*)(x + (size_t)n * NTOT + s0 + 4 * s4);
        *(uint2*)(X2 + n * 68 + 2 * s4) = pk4(v);
    }
    #pragma unroll
    for (int it = 0; it < 4; it++) {               // lb -> half2 [q][t][20]
        int i = tid + 256 * it;
        int q = i >> 8, t = (i >> 3) & 31, s4 = i & 7;
        float4 v = *(const float4*)(lb + (size_t)(slice * 4 + q) * 1024 + t * 32 + 4 * s4);
        *(uint2*)(LB2 + q * 640 + t * 20 + 2 * s4) = pk4(v);
    }
    float4 pt[3];
    #pragma unroll
    for (int it = 0; it < 3; it++) {
        int i = tid + 256 * it;
        if (i < 512) pt[it] = t_load(0, i, slice);
    }
    cpa_wait0();
    __syncthreads();

    float acc[4][4];
    #pragma unroll
    for (int j = 0; j < 4; j++) { acc[j][0] = acc[j][1] = acc[j][2] = acc[j][3] = 0.f; }

    {   // leaf: A = x (q-block cols), B = lb packed
        const uint32_t* Xl = X2 + 16 * wm * 68 + 16 * wg;
        const uint32_t* Bq = LB2 + wg * 640;
        #pragma unroll
        for (int kc = 0; kc < 2; kc++) {
            uint32_t a[4];
            int k2 = t4 + 8 * kc;
            a[0] = Xl[g * 68 + k2];     a[1] = Xl[(g + 8) * 68 + k2];
            a[2] = Xl[g * 68 + k2 + 4]; a[3] = Xl[(g + 8) * 68 + k2 + 4];
            #pragma unroll
            for (int j = 0; j < 4; j++) {
                int tl = 8 * j + g;
                mma16(acc[j], a, Bq[tl * 20 + k2], Bq[tl * 20 + k2 + 4]);
            }
        }
    }
    #pragma unroll
    for (int it = 0; it < 3; it++) {               // t_store(0)
        int i = tid + 256 * it;
        if (i < 512) t_store(T2, 0, i, pt[it], s2);
    }
    __syncthreads();

    #pragma unroll 1
    for (int L = 0; L < 12; L++) {
        int cur = L & 1;
        uint32_t curw = 2176 + cur * 9216;
        if (L < 11) {
            uint32_t nxtw = 2176 + (cur ^ 1) * 9216;
            float* nx = (float*)(sm + nxtw);
            uint4 z = {0, 0, 0, 0};
            int L2 = L + 1;
            if (L2 == 9 && tid < 128) {
                *(uint4*)(nx + tid * 72 + 52) = z;
                *(uint4*)(nx + tid * 72 + 56) = z;
                *(uint4*)(nx + tid * 72 + 60) = z;
            }
            if (L2 == 11 && tid < 128) {
                *(uint4*)(nx + tid * 72 + 20) = z;
                *(uint4*)(nx + tid * 72 + 24) = z;
                *(uint4*)(nx + tid * 72 + 28) = z;
            }
            epi_issueU(smb, nxtw, p.u[L2], L2, slice, tid);
            cpa_commit();
            int tc2 = t_count(L2);
            #pragma unroll
            for (int it = 0; it < 3; it++) {
                int i = tid + 256 * it;
                if (i < tc2) pt[it] = t_load(L2, i, slice);
            }
        }

        int astride = (L <= 9) ? 36 : 20;
        int nch = (L <= 9) ? 4 : 2;
        const uint32_t* Ab = T2;
        if (L == 10) Ab = T2 + (wg >> 1) * 640;
        else if (L == 11) Ab = T2 + wg * 640;
        const uint32_t* Arow = Ab + 16 * wm * astride;
        const float* Bs = (const float*)(sm + curw) + 32 * wg * 72;
        for (int kc = 0; kc < nch; kc++) {
            uint32_t a[4];
            int k2 = t4 + 8 * kc;
            a[0] = Arow[g * astride + k2];     a[1] = Arow[(g + 8) * astride + k2];
            a[2] = Arow[g * astride + k2 + 4]; a[3] = Arow[(g + 8) * astride + k2 + 4];
            #pragma unroll
            for (int j = 0; j < 4; j++) {
                int sl = 8 * j + g;
                float2 f0 = *(const float2*)(Bs + sl * 72 + 16 * kc + 2 * t4);
                float2 f1 = *(const float2*)(Bs + sl * 72 + 16 * kc + 2 * t4 + 8);
                mma16(acc[j], a, pkh2(f0.x, f0.y), pkh2(f1.x, f1.y));
            }
        }

        if (L < 11) {
            cpa_wait0();
            __syncthreads();
            int L2 = L + 1;
            if (L2 == 9 && tid < 128) {            // zero t pads k 56..63 (NaN safety)
                int n = tid >> 2;
                T2[n * 36 + 28 + (tid & 3)] = 0;
            }
            if (L2 == 11 && tid < 128) {           // zero t pads r2 10..15 per slot-row
                uint2 z2 = {0, 0};
                uint32_t* b = T2 + (tid >> 5) * 640 + (tid & 31) * 20;
                *(uint2*)(b + 10) = z2; *(uint2*)(b + 12) = z2; *(uint2*)(b + 14) = z2;
            }
            int tc2 = t_count(L2);
            #pragma unroll
            for (int it = 0; it < 3; it++) {
                int i = tid + 256 * it;
                if (i < tc2) t_store(T2, L2, i, pt[it], s2);
            }
            __syncthreads();
        }
    }

    int n1 = 16 * wm + g;
    #pragma unroll
    for (int j = 0; j < 4; j++) {
        int sl = s0 + 32 * wg + 8 * j + 2 * t4;
        *(float2*)(out + (size_t)n1 * NTOT + sl)       = make_float2(acc[j][0], acc[j][1]);
        *(float2*)(out + (size_t)(n1 + 8) * NTOT + sl) = make_float2(acc[j][2], acc[j][3]);
    }
}

// ---------- driver ----------
extern "C" void kernel_launch(void* const* d_in, const int* in_sizes, int n_in,
                              void* d_out, int out_size) {
    (void)in_sizes; (void)n_in; (void)out_size;
    const float* x  = (const float*)d_in[0];
    const float* lb = (const float*)d_in[1];
    const float* sc = (const float*)d_in[2];
    P p;
    for (int l = 0; l < 12; l++) p.u[l] = (const float*)d_in[3 + l];
    float* out = (float*)d_out;

    cudaFuncSetAttribute(k_p1,  cudaFuncAttributeMaxDynamicSharedMemorySize, P1_SM);
    cudaFuncSetAttribute(k_epi, cudaFuncAttributeMaxDynamicSharedMemorySize, E_SM);

    k_zero_t<<<(ZERON / 4 + 255) / 256, 256>>>();
    k_p1<<<1024, 256, P1_SM>>>(p, x);
    k_epi<<<1024, 256, E_SM>>>(p, lb, x, sc, out);
}

// round 15
// speedup vs baseline: 1.4007x; 1.0108x over previous
#include <cuda_runtime.h>
#include <cstdint>

#define NTOT 131072

__device__ __align__(16) float g_t[9170944];
__constant__ int c_OFF[12] = {0,4096,12288,28672,61440,126976,258048,520192,
                              1044480,2093056,3928064,6025216};
__constant__ int c_R[12] = {64,64,64,64,64,64,64,64,64,52,32,20};
__constant__ unsigned c_MUL[12] = {65536,65536,65536,65536,65536,65536,65536,65536,
                                   65536,80660,131072,209716};   // ceil(2^20/Rq)
#define ZERON 1044480   // levels 0-7 atomic region only

struct P { const float* u[12]; };

// ---------- helpers ----------
__device__ __forceinline__ uint32_t pkh2(float lo, float hi) {   // half2 {lo, hi}
    uint32_t r; asm("cvt.rn.f16x2.f32 %0, %1, %2;" : "=r"(r) : "f"(hi), "f"(lo)); return r;
}
__device__ __forceinline__ uint2 pk4(float4 v) {
    uint2 o; o.x = pkh2(v.x, v.y); o.y = pkh2(v.z, v.w); return o;
}
__device__ __forceinline__ uint2 pk4s(float4 v, float s) {
    uint2 o; o.x = pkh2(v.x * s, v.y * s); o.y = pkh2(v.z * s, v.w * s); return o;
}
__device__ __forceinline__ void mma16(float* c, const uint32_t* a, uint32_t b0, uint32_t b1) {
    asm volatile("mma.sync.aligned.m16n8k16.row.col.f32.f16.f16.f32 "
        "{%0,%1,%2,%3}, {%4,%5,%6,%7}, {%8,%9}, {%0,%1,%2,%3};"
        : "+f"(c[0]), "+f"(c[1]), "+f"(c[2]), "+f"(c[3])
        : "r"(a[0]), "r"(a[1]), "r"(a[2]), "r"(a[3]), "r"(b0), "r"(b1));
}
__device__ __forceinline__ void red4(float* p, float4 v) {
    asm volatile("red.global.add.v4.f32 [%0], {%1,%2,%3,%4};"
        :: "l"(p), "f"(v.x), "f"(v.y), "f"(v.z), "f"(v.w) : "memory");
}
__device__ __forceinline__ uint32_t smem_u32(const void* p) {
    uint32_t a; asm("{ .reg .u64 t; cvta.to.shared.u64 t, %1; cvt.u32.u64 %0, t; }" : "=r"(a) : "l"(p));
    return a;
}
__device__ __forceinline__ void cpa16(uint32_t dst, const void* src) {
    asm volatile("cp.async.cg.shared.global [%0], [%1], 16;" :: "r"(dst), "l"(src) : "memory");
}
__device__ __forceinline__ void cpa_commit() { asm volatile("cp.async.commit_group;" ::: "memory"); }
__device__ __forceinline__ void cpa_wait0()  { asm volatile("cp.async.wait_group 0;" ::: "memory"); }

// pack 4 contiguous output cols per thread via bfly(1); returns row/col via refs
__device__ __forceinline__ float4 pack_v4(const float* a, int t4, int n1, int nb, int j,
                                          int& row, int& col) {
    float s0_ = (t4 & 1) ? a[0] : a[2];
    float s1_ = (t4 & 1) ? a[1] : a[3];
    float r0 = __shfl_xor_sync(0xffffffffu, s0_, 1);
    float r1 = __shfl_xor_sync(0xffffffffu, s1_, 1);
    float4 vv;
    if (t4 & 1) { vv = make_float4(r0, r1, a[2], a[3]); row = n1 + 8; col = nb + 8 * j + 2 * t4 - 2; }
    else        { vv = make_float4(a[0], a[1], r0, r1); row = n1;     col = nb + 8 * j + 2 * t4; }
    return vv;
}

__global__ void k_zero_t() {
    int i = blockIdx.x * blockDim.x + threadIdx.x;
    if (i < ZERON / 4) ((float4*)g_t)[i] = make_float4(0.f, 0.f, 0.f, 0.f);
}

// stage U[L] (fp32) via cp.async: p1 layout [s][68] with block-diag cols
__device__ __forceinline__ void p1_issueU(uint32_t smb, uint32_t dstw, const float* U,
                                          int L, int slice, int tid) {
    int Rq = c_R[L] >> 2, tot = 128 * Rq;
    unsigned MUL = c_MUL[L];
    const float4* U4 = (const float4*)U + (size_t)slice * (size_t)(32 * c_R[L]);
    #pragma unroll
    for (int it = 0; it < 8; it++) {
        int i = tid + 256 * it;
        if (i < tot) {
            int s = (int)(((unsigned)i * MUL) >> 20);
            int r4 = i - s * Rq;
            int col = (L <= 9) ? 4 * r4
                    : (L == 10 ? ((s >> 6) & 1) * 32 + 4 * r4
                               : ((s >> 5) & 1) * 24 + 4 * r4);
            cpa16(smb + (dstw + s * 68 + col) * 4, U4 + i);
        }
    }
}
// epi layout [s][72] straight cols
__device__ __forceinline__ void epi_issueU(uint32_t smb, uint32_t dstw, const float* U,
                                           int L, int slice, int tid) {
    int Rq = c_R[L] >> 2, tot = 128 * Rq;
    unsigned MUL = c_MUL[L];
    const float4* U4 = (const float4*)U + (size_t)slice * (size_t)(32 * c_R[L]);
    #pragma unroll
    for (int it = 0; it < 8; it++) {
        int i = tid + 256 * it;
        if (i < tot) {
            int s = (int)(((unsigned)i * MUL) >> 20);
            int r4 = i - s * Rq;
            cpa16(smb + (dstw + s * 72 + 4 * r4) * 4, U4 + i);
        }
    }
}

// ================= phase 1: group of 2 slices, level-outer, register K-merge =================
// words: X2[2][2176] half2 | usA[8704] fp32 | usB[8704] fp32
#define P1_SM (21760 * 4)
__global__ void __launch_bounds__(256, 2) k_p1(P p, const float* __restrict__ x) {
    extern __shared__ __align__(16) uint32_t sm[];
    uint32_t* X2 = sm;
    uint32_t smb = smem_u32(sm);
    int tid = threadIdx.x, w = tid >> 5, lane = tid & 31;
    int g = lane >> 2, t4 = lane & 3;
    int wm = w >> 2, wg = w & 3;
    int grp = blockIdx.x, base = grp * 2;

    #pragma unroll
    for (int it = 0; it < 8; it++) {               // stage x both slices -> half2 [q][n][68]
        int i = tid + 256 * it;
        int q = i >> 10, j = i & 1023;
        int n = j >> 5, s4 = j & 31;
        float4 v = *(const float4*)(x + (size_t)n * NTOT + grp * 256 + q * 128 + 4 * s4);
        *(uint2*)(X2 + q * 2176 + n * 68 + 2 * s4) = pk4(v);
    }
    p1_issueU(smb, 4352, p.u[0], 0, base, tid);
    cpa_commit();
    cpa_wait0();
    __syncthreads();

    float acc[3][4];
    #pragma unroll 1
    for (int step = 0; step < 24; step++) {
        int L = step >> 1, q = step & 1, slice = base + q;
        uint32_t curw = 4352 + (step & 1) * 8704;
        if (step < 23) {
            int L2 = (step + 1) >> 1, q2 = (step + 1) & 1;
            uint32_t nxtw = 4352 + ((step + 1) & 1) * 8704;
            float* nx = (float*)(sm + nxtw);
            uint4 z = {0, 0, 0, 0};
            if (L2 == 9 && tid < 128) *(uint4*)(nx + tid * 68 + 52) = z;
            if (L2 == 11 && tid < 128) {
                *(uint4*)(nx + tid * 68 + 20) = z;
                *(uint4*)(nx + tid * 68 + 44) = z;
            }
            p1_issueU(smb, nxtw, p.u[L2], L2, base + q2, tid);
            cpa_commit();
        }

        int ntile = (L == 11) ? 3 : 2;
        int nb = (L == 11) ? 24 * (wg & 1) : 16 * wg;
        int kc0 = 0, kc1 = 8;
        if (L == 10) { kc0 = 4 * (wg >> 1); kc1 = kc0 + 4; }
        if (L == 11) { kc0 = 2 * wg;        kc1 = kc0 + 2; }

        if (q == 0 || L >= 9) {
            #pragma unroll
            for (int j = 0; j < 3; j++) { acc[j][0] = acc[j][1] = acc[j][2] = acc[j][3] = 0.f; }
        }

        const uint32_t* X = X2 + q * 2176 + 16 * wm * 68;
        const float* Bf = (const float*)(sm + curw);
        for (int kc = kc0; kc < kc1; kc++) {
            uint32_t a[4];
            int k2 = t4 + 8 * kc;
            a[0] = X[g * 68 + k2];       a[1] = X[(g + 8) * 68 + k2];
            a[2] = X[g * 68 + k2 + 4];   a[3] = X[(g + 8) * 68 + k2 + 4];
            const float* Br0 = Bf + (16 * kc + 2 * t4) * 68;
            #pragma unroll
            for (int j = 0; j < 3; j++)
                if (j < ntile) {
                    int np = nb + 8 * j + g;
                    uint32_t b0 = pkh2(Br0[np],           Br0[np + 68]);
                    uint32_t b1 = pkh2(Br0[np + 8 * 68],  Br0[np + 9 * 68]);
                    mma16(acc[j], a, b0, b1);
                }
        }

        if (L >= 9 || q == 1) {                    // flush (shfl-packed v4)
            int n1 = 16 * wm + g;
            #pragma unroll
            for (int j = 0; j < 3; j++) {
                if (j < ntile) {
                    int row, col;
                    float4 vv = pack_v4(acc[j], t4, n1, nb, j, row, col);
                    if (L <= 7) {
                        int blk = slice >> (9 - L);
                        red4(g_t + c_OFF[L] + (size_t)blk * 2048 + row * 64 + col, vv);
                    } else if (L == 8) {
                        *(float4*)(g_t + c_OFF[8] + (size_t)grp * 2048 + row * 64 + col) = vv;
                    } else if (L == 9) {
                        if (col < 56)
                            *(float4*)(g_t + c_OFF[9] + (size_t)slice * 1792 + row * 56 + col) = vv;
                    } else if (L == 10) {
                        int blk = slice * 2 + (col >> 5), r = col & 31;
                        *(float4*)(g_t + c_OFF[10] + (size_t)blk * 1024 + row * 32 + r) = vv;
                    } else {
                        int blk = slice * 4 + wg, r = col - nb;
                        *(float4*)(g_t + c_OFF[11] + (size_t)blk * 768 + row * 24 + r) = vv;
                    }
                }
            }
        }
        if (step < 23) { cpa_wait0(); __syncthreads(); }
    }
}

// ---------- epilogue t helpers ----------
__device__ __forceinline__ int t_count(int L) {
    return (L <= 8 || L == 10) ? 512 : (L == 9 ? 448 : 768);
}
__device__ __forceinline__ float4 t_load(int L, int i, int slice) {
    const float4* b;
    if (L <= 8)      b = (const float4*)(g_t + c_OFF[L]) + (size_t)((slice >> (9 - L)) ^ 1) * 512 + i;
    else if (L == 9) b = (const float4*)(g_t + c_OFF[9]) + (size_t)(slice ^ 1) * 448 + i;
    else if (L == 10) {
        int j = i >> 8;
        b = (const float4*)(g_t + c_OFF[10]) + (size_t)(slice * 2 + (j ^ 1)) * 256 + (i & 255);
    } else {
        int j = i / 192;
        b = (const float4*)(g_t + c_OFF[11]) + (size_t)(slice * 4 + (j ^ 1)) * 192 + (i - 192 * j);
    }
    return *b;
}
// T2 half2 layouts: L<=9: [n][36]; L10: [2][32][20]; L11: [4][32][20]
__device__ __forceinline__ void t_store(uint32_t* T2, int L, int i, float4 v, float s2) {
    int off;
    if (L <= 8)      { int n = i >> 4, r4 = i & 15;                off = n * 36 + 2 * r4; }
    else if (L == 9) { int n = (int)(((unsigned)i * 74899u) >> 20); int r4 = i - 14 * n;
                       off = n * 36 + 2 * r4; }
    else if (L == 10){ int j = i >> 8, n = (i >> 3) & 31, r4 = i & 7;
                       off = j * 640 + n * 20 + 2 * r4; }
    else             { int j = i / 192, rem = i - 192 * j;
                       int n = (int)(((unsigned)rem * 174763u) >> 20); int r4 = rem - 6 * n;
                       off = j * 640 + n * 20 + 2 * r4; }
    *(uint2*)(T2 + off) = pk4s(v, s2);
}

// ================= epilogue: out[n][s] = leaf + sum_L t_sib[n][r] U[s][r] =================
// words: X2[2176] | usA[9216] | usB[9216] | T2[2560] | LB2[2560]  = 25728
#define E_SM (25728 * 4)
__global__ void __launch_bounds__(256, 2) k_epi(P p, const float* __restrict__ lb,
                                                const float* __restrict__ x,
                                                const float* __restrict__ sc,
                                                float* __restrict__ out) {
    extern __shared__ __align__(16) uint32_t sm[];
    uint32_t* X2 = sm;
    uint32_t* T2 = sm + 20608;
    uint32_t* LB2 = sm + 23168;
    uint32_t smb = smem_u32(sm);
    int tid = threadIdx.x, w = tid >> 5, lane = tid & 31;
    int g = lane >> 2, t4 = lane & 3;
    int wm = w >> 2, wg = w & 3;
    int slice = blockIdx.x, s0 = slice * 128;
    float scv = __ldg(sc), s2 = scv * scv;

    epi_issueU(smb, 2176, p.u[0], 0, slice, tid);
    cpa_commit();
    #pragma unroll
    for (int it = 0; it < 4; it++) {               // x -> half2 [n][68]
        int i = tid + 256 * it;
        int n = i >> 5, s4 = i & 31;
        float4 v = *(const float4*)(x + (size_t)n * NTOT + s0 + 4 * s4);
        *(uint2*)(X2 + n * 68 + 2 * s4) = pk4(v);
    }
    #pragma unroll
    for (int it = 0; it < 4; it++) {               // lb -> half2 [q][t][20]
        int i = tid + 256 * it;
        int q = i >> 8, t = (i >> 3) & 31, s4 = i & 7;
        float4 v = *(const float4*)(lb + (size_t)(slice * 4 + q) * 1024 + t * 32 + 4 * s4);
        *(uint2*)(LB2 + q * 640 + t * 20 + 2 * s4) = pk4(v);
    }
    float4 pt[3];
    #pragma unroll
    for (int it = 0; it < 3; it++) {
        int i = tid + 256 * it;
        if (i < 512) pt[it] = t_load(0, i, slice);
    }
    cpa_wait0();
    __syncthreads();

    float acc[4][4];
    #pragma unroll
    for (int j = 0; j < 4; j++) { acc[j][0] = acc[j][1] = acc[j][2] = acc[j][3] = 0.f; }

    {   // leaf: A = x (q-block cols), B = lb packed
        const uint32_t* Xl = X2 + 16 * wm * 68 + 16 * wg;
        const uint32_t* Bq = LB2 + wg * 640;
        #pragma unroll
        for (int kc = 0; kc < 2; kc++) {
            uint32_t a[4];
            int k2 = t4 + 8 * kc;
            a[0] = Xl[g * 68 + k2];     a[1] = Xl[(g + 8) * 68 + k2];
            a[2] = Xl[g * 68 + k2 + 4]; a[3] = Xl[(g + 8) * 68 + k2 + 4];
            #pragma unroll
            for (int j = 0; j < 4; j++) {
                int tl = 8 * j + g;
                mma16(acc[j], a, Bq[tl * 20 + k2], Bq[tl * 20 + k2 + 4]);
            }
        }
    }
    #pragma unroll
    for (int it = 0; it < 3; it++) {               // t_store(0)
        int i = tid + 256 * it;
        if (i < 512) t_store(T2, 0, i, pt[it], s2);
    }
    __syncthreads();

    #pragma unroll 1
    for (int L = 0; L < 12; L++) {
        int cur = L & 1;
        uint32_t curw = 2176 + cur * 9216;
        if (L < 11) {
            uint32_t nxtw = 2176 + (cur ^ 1) * 9216;
            float* nx = (float*)(sm + nxtw);
            uint4 z = {0, 0, 0, 0};
            int L2 = L + 1;
            if (L2 == 9 && tid < 128) {
                *(uint4*)(nx + tid * 72 + 52) = z;
                *(uint4*)(nx + tid * 72 + 56) = z;
                *(uint4*)(nx + tid * 72 + 60) = z;
            }
            if (L2 == 11 && tid < 128) {
                *(uint4*)(nx + tid * 72 + 20) = z;
                *(uint4*)(nx + tid * 72 + 24) = z;
                *(uint4*)(nx + tid * 72 + 28) = z;
            }
            epi_issueU(smb, nxtw, p.u[L2], L2, slice, tid);
            cpa_commit();
            int tc2 = t_count(L2);
            #pragma unroll
            for (int it = 0; it < 3; it++) {
                int i = tid + 256 * it;
                if (i < tc2) pt[it] = t_load(L2, i, slice);
            }
        }

        int astride = (L <= 9) ? 36 : 20;
        int nch = (L <= 9) ? 4 : 2;
        const uint32_t* Ab = T2;
        if (L == 10) Ab = T2 + (wg >> 1) * 640;
        else if (L == 11) Ab = T2 + wg * 640;
        const uint32_t* Arow = Ab + 16 * wm * astride;
        const float* Bs = (const float*)(sm + curw) + 32 * wg * 72;
        for (int kc = 0; kc < nch; kc++) {
            uint32_t a[4];
            int k2 = t4 + 8 * kc;
            a[0] = Arow[g * astride + k2];     a[1] = Arow[(g + 8) * astride + k2];
            a[2] = Arow[g * astride + k2 + 4]; a[3] = Arow[(g + 8) * astride + k2 + 4];
            #pragma unroll
            for (int j = 0; j < 4; j++) {
                int sl = 8 * j + g;
                float2 f0 = *(const float2*)(Bs + sl * 72 + 16 * kc + 2 * t4);
                float2 f1 = *(const float2*)(Bs + sl * 72 + 16 * kc + 2 * t4 + 8);
                mma16(acc[j], a, pkh2(f0.x, f0.y), pkh2(f1.x, f1.y));
            }
        }

        if (L < 11) {
            cpa_wait0();
            __syncthreads();
            int L2 = L + 1;
            if (L2 == 9 && tid < 128) {            // zero t pads k 56..63 (NaN safety)
                int n = tid >> 2;
                T2[n * 36 + 28 + (tid & 3)] = 0;
            }
            if (L2 == 11 && tid < 128) {           // zero t pads r2 10..15 per slot-row
                uint2 z2 = {0, 0};
                uint32_t* b = T2 + (tid >> 5) * 640 + (tid & 31) * 20;
                *(uint2*)(b + 10) = z2; *(uint2*)(b + 12) = z2; *(uint2*)(b + 14) = z2;
            }
            int tc2 = t_count(L2);
            #pragma unroll
            for (int it = 0; it < 3; it++) {
                int i = tid + 256 * it;
                if (i < tc2) t_store(T2, L2, i, pt[it], s2);
            }
            __syncthreads();
        }
    }

    int n1 = 16 * wm + g;
    #pragma unroll
    for (int j = 0; j < 4; j++) {                  // shfl-packed STG.128 out
        int row, col;
        float4 vv = pack_v4(acc[j], t4, n1, 32 * wg, j, row, col);
        *(float4*)(out + (size_t)row * NTOT + s0 + col) = vv;
    }
}

// ---------- driver ----------
extern "C" void kernel_launch(void* const* d_in, const int* in_sizes, int n_in,
                              void* d_out, int out_size) {
    (void)in_sizes; (void)n_in; (void)out_size;
    const float* x  = (const float*)d_in[0];
    const float* lb = (const float*)d_in[1];
    const float* sc = (const float*)d_in[2];
    P p;
    for (int l = 0; l < 12; l++) p.u[l] = (const float*)d_in[3 + l];
    float* out = (float*)d_out;

    cudaFuncSetAttribute(k_p1,  cudaFuncAttributeMaxDynamicSharedMemorySize, P1_SM);
    cudaFuncSetAttribute(k_epi, cudaFuncAttributeMaxDynamicSharedMemorySize, E_SM);

    k_zero_t<<<(ZERON / 4 + 255) / 256, 256>>>();
    k_p1<<<512, 256, P1_SM>>>(p, x);
    k_epi<<<1024, 256, E_SM>>>(p, lb, x, sc, out);
}